// round 15
// baseline (speedup 1.0000x reference)
#include <cuda_runtime.h>
#include <cstdint>

#define N_NODES 50000
#define N_EDGES 800000
#define NE_TOT  (N_EDGES + N_NODES)   // 850000, self loops appended
#define NG 16

typedef unsigned long long ull;

// ---------------- scratch ----------------
__device__ __align__(16) float g_big1[N_NODES * 192];   // 0-63 xl1 | 64-127 xr1 | 128-191 hproj1
__device__ __align__(16) float g_big2[N_NODES * 96];    // 0-31 xl2 | 32-63 xr2 | 64-95 hproj2
__device__ __align__(16) float g_acc1[N_NODES * 64];
__device__ __align__(16) float g_den1[N_NODES * 2];
__device__ __align__(16) float g_acc2[N_NODES * 32];
__device__ __align__(16) float g_den2[N_NODES];
__device__ __align__(16) float g_Wcat1[128 * 192];
__device__ __align__(16) float g_bcat1[192];
__device__ __align__(16) float g_Wcat2[64 * 96];
__device__ __align__(16) float g_bcat2[96];
__device__ __align__(16) float g_easum[16];
__device__ __align__(16) float g_eself1[64];
__device__ __align__(16) float g_eself2[32];
__device__ __align__(16) float g_bnsum[128];     // [0:64) sum, [64:128) sumsq
__device__ __align__(16) float g_bnsc1[128];     // [0:64) scale, [64:128) shift
__device__ __align__(16) float g_bnsum2[64];
__device__ __align__(16) float g_bnsc2[64];
__device__ __align__(16) float g_psum[NG * 32];
__device__ __align__(16) float g_pmax[NG * 32];
__device__ int g_cnt[NG];

// ---------------- helpers ----------------
__device__ __forceinline__ ull pk2(float a, float b) {
    ull r; asm("mov.b64 %0,{%1,%2};" : "=l"(r) : "f"(a), "f"(b)); return r;
}
__device__ __forceinline__ float2 up2(ull v) {
    float2 r; asm("mov.b64 {%0,%1},%2;" : "=f"(r.x), "=f"(r.y) : "l"(v)); return r;
}
__device__ __forceinline__ ull fma2(ull a, ull b, ull c) {
    ull d; asm("fma.rn.f32x2 %0,%1,%2,%3;" : "=l"(d) : "l"(a), "l"(b), "l"(c)); return d;
}
__device__ __forceinline__ float lrelu(float v) { return v > 0.f ? v : 0.2f * v; }

__device__ __forceinline__ void red4(float* p, float4 v) {
    asm volatile("red.global.add.v4.f32 [%0], {%1,%2,%3,%4};"
                 :: "l"(p), "f"(v.x), "f"(v.y), "f"(v.z), "f"(v.w) : "memory");
}

__device__ __forceinline__ void atomicMaxF(float* addr, float v) {
    if (v >= 0.f) atomicMax((int*)addr, __float_as_int(v));
    else          atomicMin((unsigned int*)addr, __float_as_uint(v));
}

// ---------------- clear (vectorized) ----------------
__global__ void clear_kernel() {
    int i  = blockIdx.x * blockDim.x + threadIdx.x;
    int st = gridDim.x * blockDim.x;
    float4 z4 = make_float4(0.f, 0.f, 0.f, 0.f);
    float4* a1 = (float4*)g_acc1;
    float4* a2 = (float4*)g_acc2;
    for (int j = i; j < N_NODES * 16; j += st) a1[j] = z4;
    for (int j = i; j < N_NODES * 8;  j += st) a2[j] = z4;
    float2* d1 = (float2*)g_den1;
    for (int j = i; j < N_NODES; j += st) { d1[j] = make_float2(0.f, 0.f); g_den2[j] = 0.f; }
    if (i < 16)  g_easum[i] = 0.f;
    if (i < 128) g_bnsum[i] = 0.f;
    if (i < 64)  g_bnsum2[i] = 0.f;
    if (i < NG * 32) { g_psum[i] = 0.f; g_pmax[i] = __int_as_float(0xff800000); }
    if (i < NG)  g_cnt[i] = 0;
}

// ---------------- weight packing ----------------
__global__ void pack1_kernel(const float* __restrict__ Wl, const float* __restrict__ bl,
                             const float* __restrict__ Wr, const float* __restrict__ br,
                             const float* __restrict__ Ws, const float* __restrict__ bs) {
    int i = blockIdx.x * blockDim.x + threadIdx.x;
    if (i < 128 * 64) {
        int k = i >> 6, j = i & 63;
        g_Wcat1[k * 192 + j]       = Wl[i];
        g_Wcat1[k * 192 + 64 + j]  = Wr[i];
        g_Wcat1[k * 192 + 128 + j] = Ws[i];
    }
    if (i < 64) { g_bcat1[i] = bl[i]; g_bcat1[64 + i] = br[i]; g_bcat1[128 + i] = bs[i]; }
}

__global__ void pack2_kernel(const float* __restrict__ Wl, const float* __restrict__ bl,
                             const float* __restrict__ Wr, const float* __restrict__ br,
                             const float* __restrict__ Ws, const float* __restrict__ bs) {
    int i = blockIdx.x * blockDim.x + threadIdx.x;
    if (i < 64 * 32) {
        int k = i >> 5, j = i & 31;
        g_Wcat2[k * 96 + j]      = Wl[i];
        g_Wcat2[k * 96 + 32 + j] = Wr[i];
        g_Wcat2[k * 96 + 64 + j] = Ws[i];
    }
    if (i < 32) { g_bcat2[i] = bl[i]; g_bcat2[32 + i] = br[i]; g_bcat2[64 + i] = bs[i]; }
}

// ---------------- edge_attr column sums ----------------
__global__ void easum_kernel(const float4* __restrict__ ea4) {
    const int NT = N_EDGES * 4;
    int tid = blockIdx.x * blockDim.x + threadIdx.x;
    int st  = gridDim.x * blockDim.x;
    int grp = tid & 3;
    float4 s = make_float4(0.f, 0.f, 0.f, 0.f);
    int i = tid;
    for (; i + 3 * st < NT; i += 4 * st) {
        float4 v0 = ea4[i];
        float4 v1 = ea4[i + st];
        float4 v2 = ea4[i + 2 * st];
        float4 v3 = ea4[i + 3 * st];
        s.x += v0.x + v1.x + v2.x + v3.x;
        s.y += v0.y + v1.y + v2.y + v3.y;
        s.z += v0.z + v1.z + v2.z + v3.z;
        s.w += v0.w + v1.w + v2.w + v3.w;
    }
    for (; i < NT; i += st) {
        float4 v = ea4[i];
        s.x += v.x; s.y += v.y; s.z += v.z; s.w += v.w;
    }
    __shared__ float sm[16];
    if (threadIdx.x < 16) sm[threadIdx.x] = 0.f;
    __syncthreads();
    atomicAdd(&sm[grp * 4 + 0], s.x);
    atomicAdd(&sm[grp * 4 + 1], s.y);
    atomicAdd(&sm[grp * 4 + 2], s.z);
    atomicAdd(&sm[grp * 4 + 3], s.w);
    __syncthreads();
    if (threadIdx.x < 16) atomicAdd(&g_easum[threadIdx.x], sm[threadIdx.x]);
}

__global__ void eself_kernel(const float* __restrict__ We1, const float* __restrict__ We2) {
    __shared__ float m[16];
    int t = threadIdx.x;
    if (t < 16) m[t] = g_easum[t] * (1.0f / N_EDGES);
    __syncthreads();
    if (t < 64) {
        float s = 0.f;
        #pragma unroll
        for (int k = 0; k < 16; k++) s += m[k] * We1[k * 64 + t];
        g_eself1[t] = s;
    }
    if (t < 32) {
        float s = 0.f;
        #pragma unroll
        for (int k = 0; k < 16; k++) s += m[k] * We2[k * 32 + t];
        g_eself2[t] = s;
    }
}

// ---------------- tiled GEMM 1 with fma.rn.f32x2 (validated) ----------------
__global__ void gemm1_kernel(const float* __restrict__ A) {
    const int K = 128, NT = 192;
    __shared__ __align__(16) float As[16 * 68];
    __shared__ __align__(8)  float Bs[16 * 100];
    const int bm = blockIdx.x * 64;
    const int bn = blockIdx.y * 96;
    const int tid = threadIdx.x;
    const int tx = tid & 15, ty = tid >> 4;
    ull acc[4][3];
    #pragma unroll
    for (int i = 0; i < 4; i++)
        #pragma unroll
        for (int j = 0; j < 3; j++) acc[i][j] = 0ull;
    const int ar = tid >> 2, ac = (tid & 3) << 2;
    for (int k0 = 0; k0 < K; k0 += 16) {
        float4 av = make_float4(0.f, 0.f, 0.f, 0.f);
        int row = bm + ar;
        if (row < N_NODES) av = *(const float4*)&A[(size_t)row * K + k0 + ac];
        As[(ac + 0) * 68 + ar] = av.x;
        As[(ac + 1) * 68 + ar] = av.y;
        As[(ac + 2) * 68 + ar] = av.z;
        As[(ac + 3) * 68 + ar] = av.w;
        #pragma unroll
        for (int i = 0; i < 6; i++) {
            int idx = tid + (i << 8);
            int r = idx / 96, cc = idx - r * 96;
            Bs[r * 100 + cc] = g_Wcat1[(k0 + r) * NT + bn + cc];
        }
        __syncthreads();
        #pragma unroll
        for (int kk = 0; kk < 16; kk++) {
            float4 a = *(const float4*)&As[kk * 68 + (ty << 2)];
            ull b0 = *(const ull*)&Bs[kk * 100 + tx * 6];
            ull b1 = *(const ull*)&Bs[kk * 100 + tx * 6 + 2];
            ull b2 = *(const ull*)&Bs[kk * 100 + tx * 6 + 4];
            ull ap;
            ap = pk2(a.x, a.x);
            acc[0][0] = fma2(ap, b0, acc[0][0]); acc[0][1] = fma2(ap, b1, acc[0][1]); acc[0][2] = fma2(ap, b2, acc[0][2]);
            ap = pk2(a.y, a.y);
            acc[1][0] = fma2(ap, b0, acc[1][0]); acc[1][1] = fma2(ap, b1, acc[1][1]); acc[1][2] = fma2(ap, b2, acc[1][2]);
            ap = pk2(a.z, a.z);
            acc[2][0] = fma2(ap, b0, acc[2][0]); acc[2][1] = fma2(ap, b1, acc[2][1]); acc[2][2] = fma2(ap, b2, acc[2][2]);
            ap = pk2(a.w, a.w);
            acc[3][0] = fma2(ap, b0, acc[3][0]); acc[3][1] = fma2(ap, b1, acc[3][1]); acc[3][2] = fma2(ap, b2, acc[3][2]);
        }
        __syncthreads();
    }
    #pragma unroll
    for (int i = 0; i < 4; i++) {
        int r = bm + (ty << 2) + i;
        if (r < N_NODES) {
            #pragma unroll
            for (int j = 0; j < 3; j++) {
                float2 v = up2(acc[i][j]);
                int cc = bn + tx * 6 + 2 * j;
                g_big1[(size_t)r * NT + cc]     = v.x + g_bcat1[cc];
                g_big1[(size_t)r * NT + cc + 1] = v.y + g_bcat1[cc + 1];
            }
        }
    }
}

// ---------------- GEMM 2 with elu1 FUSED into the A-tile load (validated R13) ----------------
__global__ void gemm2_kernel(const float* __restrict__ bias1) {
    const int K = 64, NT = 96;
    __shared__ __align__(16) float As[16 * 68];
    __shared__ __align__(8)  float Bs[16 * 100];
    const int bm = blockIdx.x * 64;
    const int bn = 0;
    const int tid = threadIdx.x;
    const int tx = tid & 15, ty = tid >> 4;
    ull acc[4][3];
    #pragma unroll
    for (int i = 0; i < 4; i++)
        #pragma unroll
        for (int j = 0; j < 3; j++) acc[i][j] = 0ull;
    const int ar = tid >> 2, ac = (tid & 3) << 2;
    for (int k0 = 0; k0 < K; k0 += 16) {
        float4 av = make_float4(0.f, 0.f, 0.f, 0.f);
        int row = bm + ar;
        if (row < N_NODES) {
            int cc = k0 + ac;
            float invd = 1.0f / (g_den1[row * 2 + (cc >> 5)] + 1e-16f);
            float4 a4 = *(const float4*)&g_acc1[(size_t)row * 64 + cc];
            float4 p4 = *(const float4*)&g_big1[(size_t)row * 192 + 128 + cc];
            float t;
            t = (a4.x * invd + bias1[cc + 0]) * g_bnsc1[cc + 0] + g_bnsc1[64 + cc + 0] + p4.x;
            av.x = t > 0.f ? t : expm1f(t);
            t = (a4.y * invd + bias1[cc + 1]) * g_bnsc1[cc + 1] + g_bnsc1[64 + cc + 1] + p4.y;
            av.y = t > 0.f ? t : expm1f(t);
            t = (a4.z * invd + bias1[cc + 2]) * g_bnsc1[cc + 2] + g_bnsc1[64 + cc + 2] + p4.z;
            av.z = t > 0.f ? t : expm1f(t);
            t = (a4.w * invd + bias1[cc + 3]) * g_bnsc1[cc + 3] + g_bnsc1[64 + cc + 3] + p4.w;
            av.w = t > 0.f ? t : expm1f(t);
        }
        As[(ac + 0) * 68 + ar] = av.x;
        As[(ac + 1) * 68 + ar] = av.y;
        As[(ac + 2) * 68 + ar] = av.z;
        As[(ac + 3) * 68 + ar] = av.w;
        #pragma unroll
        for (int i = 0; i < 6; i++) {
            int idx = tid + (i << 8);
            int r = idx / 96, cc = idx - r * 96;
            Bs[r * 100 + cc] = g_Wcat2[(k0 + r) * NT + bn + cc];
        }
        __syncthreads();
        #pragma unroll
        for (int kk = 0; kk < 16; kk++) {
            float4 a = *(const float4*)&As[kk * 68 + (ty << 2)];
            ull b0 = *(const ull*)&Bs[kk * 100 + tx * 6];
            ull b1 = *(const ull*)&Bs[kk * 100 + tx * 6 + 2];
            ull b2 = *(const ull*)&Bs[kk * 100 + tx * 6 + 4];
            ull ap;
            ap = pk2(a.x, a.x);
            acc[0][0] = fma2(ap, b0, acc[0][0]); acc[0][1] = fma2(ap, b1, acc[0][1]); acc[0][2] = fma2(ap, b2, acc[0][2]);
            ap = pk2(a.y, a.y);
            acc[1][0] = fma2(ap, b0, acc[1][0]); acc[1][1] = fma2(ap, b1, acc[1][1]); acc[1][2] = fma2(ap, b2, acc[1][2]);
            ap = pk2(a.z, a.z);
            acc[2][0] = fma2(ap, b0, acc[2][0]); acc[2][1] = fma2(ap, b1, acc[2][1]); acc[2][2] = fma2(ap, b2, acc[2][2]);
            ap = pk2(a.w, a.w);
            acc[3][0] = fma2(ap, b0, acc[3][0]); acc[3][1] = fma2(ap, b1, acc[3][1]); acc[3][2] = fma2(ap, b2, acc[3][2]);
        }
        __syncthreads();
    }
    #pragma unroll
    for (int i = 0; i < 4; i++) {
        int r = bm + (ty << 2) + i;
        if (r < N_NODES) {
            #pragma unroll
            for (int j = 0; j < 3; j++) {
                float2 v = up2(acc[i][j]);
                int cc = bn + tx * 6 + 2 * j;
                g_big2[(size_t)r * NT + cc]     = v.x + g_bcat2[cc];
                g_big2[(size_t)r * NT + cc + 1] = v.y + g_bcat2[cc + 1];
            }
        }
    }
}

// ---------------- edge kernel layer 1 (smem-We; 3 edges in flight) ----------------
__global__ void edge1_kernel(const int* __restrict__ ei, const float* __restrict__ ea,
                             const float* __restrict__ We, const float* __restrict__ att) {
    __shared__ __align__(16) float sWe[16 * 64];
    __shared__ __align__(16) float sAtt[64];
    __shared__ __align__(16) float sEself[64];
    for (int i = threadIdx.x; i < 16 * 64; i += blockDim.x) sWe[i] = We[i];
    if (threadIdx.x < 64) { sAtt[threadIdx.x] = att[threadIdx.x]; sEself[threadIdx.x] = g_eself1[threadIdx.x]; }
    __syncthreads();
    const int lane = threadIdx.x & 31;
    const int sub  = lane & 15;
    const int head = sub >> 3;
    const int half = lane >> 4;
    const int warp = threadIdx.x >> 5;
    const int nwarps = (gridDim.x * blockDim.x) >> 5;
    const int gw = blockIdx.x * (blockDim.x >> 5) + warp;
    const int npairs = (NE_TOT + 1) >> 1;
    const float4 a4  = *(const float4*)&sAtt[4 * sub];
    const float4 es4 = *(const float4*)&sEself[4 * sub];
    for (int p0 = gw; p0 < npairs; p0 += 3 * nwarps) {
        int   e[3];  bool v[3], lp[3];
        int   si[3], di[3];
        float eav[3];
        float4 xl[3], xr[3], e4[3];
        #pragma unroll
        for (int u = 0; u < 3; u++) {
            int p = p0 + u * nwarps;
            bool hasP = p < npairs;
            e[u] = hasP ? (p * 2 + half) : 0;
            v[u] = hasP && (e[u] < NE_TOT);
            lp[u] = false;
            si[u] = 0; di[u] = 0;
            if (v[u]) {
                if (e[u] < N_EDGES) { si[u] = ei[e[u]]; di[u] = ei[N_EDGES + e[u]]; }
                else                { si[u] = di[u] = e[u] - N_EDGES; lp[u] = true; }
            }
        }
        #pragma unroll
        for (int u = 0; u < 3; u++) {
            int ex = (v[u] && !lp[u]) ? e[u] : 0;
            eav[u] = ea[(size_t)ex * 16 + sub];
            xl[u] = *(const float4*)&g_big1[(size_t)si[u] * 192 + 4 * sub];
            xr[u] = *(const float4*)&g_big1[(size_t)di[u] * 192 + 64 + 4 * sub];
            e4[u] = make_float4(0.f, 0.f, 0.f, 0.f);
        }
        #pragma unroll
        for (int k = 0; k < 16; k++) {
            float4 w4 = *(const float4*)&sWe[k * 64 + 4 * sub];
            #pragma unroll
            for (int u = 0; u < 3; u++) {
                float a = __shfl_sync(0xffffffffu, eav[u], k, 16);
                e4[u].x += a * w4.x; e4[u].y += a * w4.y; e4[u].z += a * w4.z; e4[u].w += a * w4.w;
            }
        }
        float p_[3];
        #pragma unroll
        for (int u = 0; u < 3; u++) {
            if (lp[u]) e4[u] = es4;
            float mx = lrelu(xl[u].x + xr[u].x + e4[u].x);
            float my = lrelu(xl[u].y + xr[u].y + e4[u].y);
            float mz = lrelu(xl[u].z + xr[u].z + e4[u].z);
            float mw = lrelu(xl[u].w + xr[u].w + e4[u].w);
            p_[u] = mx * a4.x + my * a4.y + mz * a4.z + mw * a4.w;
        }
        #pragma unroll
        for (int u = 0; u < 3; u++) p_[u] += __shfl_xor_sync(0xffffffffu, p_[u], 4);
        #pragma unroll
        for (int u = 0; u < 3; u++) p_[u] += __shfl_xor_sync(0xffffffffu, p_[u], 2);
        #pragma unroll
        for (int u = 0; u < 3; u++) p_[u] += __shfl_xor_sync(0xffffffffu, p_[u], 1);
        #pragma unroll
        for (int u = 0; u < 3; u++) {
            float w = __expf(p_[u]);
            if (v[u]) {
                if ((sub & 7) == 0) atomicAdd(&g_den1[di[u] * 2 + head], w);
                red4(&g_acc1[(size_t)di[u] * 64 + 4 * sub],
                     make_float4(w * xl[u].x, w * xl[u].y, w * xl[u].z, w * xl[u].w));
            }
        }
    }
}

// ---------------- edge kernel layer 2 (smem-We; 3 quads in flight) ----------------
__global__ void edge2_kernel(const int* __restrict__ ei, const float* __restrict__ ea,
                             const float* __restrict__ We, const float* __restrict__ att) {
    __shared__ __align__(16) float sWe[16 * 32];
    __shared__ __align__(16) float sAtt[32];
    __shared__ __align__(16) float sEself[32];
    for (int i = threadIdx.x; i < 512; i += blockDim.x) sWe[i] = We[i];
    if (threadIdx.x < 32) { sAtt[threadIdx.x] = att[threadIdx.x]; sEself[threadIdx.x] = g_eself2[threadIdx.x]; }
    __syncthreads();
    const int lane = threadIdx.x & 31;
    const int grp = lane >> 3, sub = lane & 7;
    const int warp = threadIdx.x >> 5;
    const int nwarps = (gridDim.x * blockDim.x) >> 5;
    const int gw = blockIdx.x * (blockDim.x >> 5) + warp;
    const int nquads = (NE_TOT + 3) >> 2;
    const float4 a4  = *(const float4*)&sAtt[4 * sub];
    const float4 es4 = *(const float4*)&sEself[4 * sub];
    for (int q0 = gw; q0 < nquads; q0 += 3 * nwarps) {
        int   e[3];  bool v[3], lp[3];
        int   si[3], di[3];
        float e0v[3], e1v[3];
        float4 xl[3], xr[3], e4[3];
        #pragma unroll
        for (int u = 0; u < 3; u++) {
            int q = q0 + u * nwarps;
            bool hasQ = q < nquads;
            e[u] = hasQ ? (q * 4 + grp) : 0;
            v[u] = hasQ && (e[u] < NE_TOT);
            lp[u] = false;
            si[u] = 0; di[u] = 0;
            if (v[u]) {
                if (e[u] < N_EDGES) { si[u] = ei[e[u]]; di[u] = ei[N_EDGES + e[u]]; }
                else                { si[u] = di[u] = e[u] - N_EDGES; lp[u] = true; }
            }
        }
        #pragma unroll
        for (int u = 0; u < 3; u++) {
            int ex = (v[u] && !lp[u]) ? e[u] : 0;
            e0v[u] = ea[(size_t)ex * 16 + sub];
            e1v[u] = ea[(size_t)ex * 16 + 8 + sub];
            xl[u] = *(const float4*)&g_big2[(size_t)si[u] * 96 + 4 * sub];
            xr[u] = *(const float4*)&g_big2[(size_t)di[u] * 96 + 32 + 4 * sub];
            e4[u] = make_float4(0.f, 0.f, 0.f, 0.f);
        }
        #pragma unroll
        for (int k = 0; k < 8; k++) {
            float4 w4 = *(const float4*)&sWe[k * 32 + 4 * sub];
            #pragma unroll
            for (int u = 0; u < 3; u++) {
                float a = __shfl_sync(0xffffffffu, e0v[u], k, 8);
                e4[u].x += a * w4.x; e4[u].y += a * w4.y; e4[u].z += a * w4.z; e4[u].w += a * w4.w;
            }
        }
        #pragma unroll
        for (int k = 0; k < 8; k++) {
            float4 w4 = *(const float4*)&sWe[(8 + k) * 32 + 4 * sub];
            #pragma unroll
            for (int u = 0; u < 3; u++) {
                float a = __shfl_sync(0xffffffffu, e1v[u], k, 8);
                e4[u].x += a * w4.x; e4[u].y += a * w4.y; e4[u].z += a * w4.z; e4[u].w += a * w4.w;
            }
        }
        float p_[3];
        #pragma unroll
        for (int u = 0; u < 3; u++) {
            if (lp[u]) e4[u] = es4;
            float mx = lrelu(xl[u].x + xr[u].x + e4[u].x);
            float my = lrelu(xl[u].y + xr[u].y + e4[u].y);
            float mz = lrelu(xl[u].z + xr[u].z + e4[u].z);
            float mw = lrelu(xl[u].w + xr[u].w + e4[u].w);
            p_[u] = mx * a4.x + my * a4.y + mz * a4.z + mw * a4.w;
        }
        #pragma unroll
        for (int u = 0; u < 3; u++) p_[u] += __shfl_xor_sync(0xffffffffu, p_[u], 4);
        #pragma unroll
        for (int u = 0; u < 3; u++) p_[u] += __shfl_xor_sync(0xffffffffu, p_[u], 2);
        #pragma unroll
        for (int u = 0; u < 3; u++) p_[u] += __shfl_xor_sync(0xffffffffu, p_[u], 1);
        #pragma unroll
        for (int u = 0; u < 3; u++) {
            float w = __expf(p_[u]);
            if (v[u]) {
                if (sub == 0) atomicAdd(&g_den2[di[u]], w);
                red4(&g_acc2[(size_t)di[u] * 32 + 4 * sub],
                     make_float4(w * xl[u].x, w * xl[u].y, w * xl[u].z, w * xl[u].w));
            }
        }
    }
}

// ---------------- BN stats layer 1 (fused) ----------------
__global__ void final1_kernel(const float* __restrict__ bias) {
    int tid = threadIdx.x;
    int c = tid & 63;
    int h = c >> 5;
    float bb = bias[c];
    float s = 0.f, q = 0.f;
    for (int n = blockIdx.x * 4 + (tid >> 6); n < N_NODES; n += gridDim.x * 4) {
        float v = g_acc1[(size_t)n * 64 + c] / (g_den1[n * 2 + h] + 1e-16f) + bb;
        s += v; q += v * v;
    }
    __shared__ float ss[256], sq[256];
    ss[tid] = s; sq[tid] = q;
    __syncthreads();
    if (tid < 64) {
        s = ss[tid] + ss[tid + 64] + ss[tid + 128] + ss[tid + 192];
        q = sq[tid] + sq[tid + 64] + sq[tid + 128] + sq[tid + 192];
        atomicAdd(&g_bnsum[tid], s);
        atomicAdd(&g_bnsum[64 + tid], q);
    }
}

__global__ void bnfin1_kernel(const float* __restrict__ g, const float* __restrict__ b) {
    int c = threadIdx.x;
    if (c < 64) {
        float mean = g_bnsum[c] * (1.0f / N_NODES);
        float var  = g_bnsum[64 + c] * (1.0f / N_NODES) - mean * mean;
        float sc   = g[c] * rsqrtf(var + 1e-5f);
        g_bnsc1[c] = sc;
        g_bnsc1[64 + c] = b[c] - mean * sc;
    }
}

// ---------------- BN stats layer 2 (fused) ----------------
__global__ void final2_kernel(const float* __restrict__ bias) {
    int tid = threadIdx.x;
    int c = tid & 31;
    float bb = bias[c];
    float s = 0.f, q = 0.f;
    for (int n = blockIdx.x * 8 + (tid >> 5); n < N_NODES; n += gridDim.x * 8) {
        float v = g_acc2[(size_t)n * 32 + c] / (g_den2[n] + 1e-16f) + bb;
        s += v; q += v * v;
    }
    __shared__ float ss[256], sq[256];
    ss[tid] = s; sq[tid] = q;
    __syncthreads();
    if (tid < 32) {
        s = 0.f; q = 0.f;
        #pragma unroll
        for (int gg = 0; gg < 8; gg++) { s += ss[tid + gg * 32]; q += sq[tid + gg * 32]; }
        atomicAdd(&g_bnsum2[tid], s);
        atomicAdd(&g_bnsum2[32 + tid], q);
    }
}

__global__ void bnfin2_kernel(const float* __restrict__ g, const float* __restrict__ b) {
    int c = threadIdx.x;
    if (c < 32) {
        float mean = g_bnsum2[c] * (1.0f / N_NODES);
        float var  = g_bnsum2[32 + c] * (1.0f / N_NODES) - mean * mean;
        float sc   = g[c] * rsqrtf(var + 1e-5f);
        g_bnsc2[c] = sc;
        g_bnsc2[32 + c] = b[c] - mean * sc;
    }
}

// ---------------- elu2 + graph pooling (batch sorted; fused recompute) ----------------
__global__ void elu2pool_kernel(const int* __restrict__ batch, const float* __restrict__ bias) {
    __shared__ float ssum[NG * 32];
    __shared__ float smax[NG * 32];
    __shared__ int scnt[NG];
    int tid = threadIdx.x;
    for (int i = tid; i < NG * 32; i += blockDim.x) { ssum[i] = 0.f; smax[i] = __int_as_float(0xff800000); }
    if (tid < NG) scnt[tid] = 0;
    __syncthreads();
    int c = tid & 31;
    float bb = bias[c];
    for (int n = blockIdx.x * 8 + (tid >> 5); n < N_NODES; n += gridDim.x * 8) {
        float v = g_acc2[(size_t)n * 32 + c] / (g_den2[n] + 1e-16f) + bb;
        v = v * g_bnsc2[c] + g_bnsc2[32 + c] + g_big2[(size_t)n * 96 + 64 + c];
        v = v > 0.f ? v : expm1f(v);
        int g = batch[n];
        atomicAdd(&ssum[g * 32 + c], v);
        if (v >= 0.f) atomicMax((int*)&smax[g * 32 + c], __float_as_int(v));
        else          atomicMin((unsigned int*)&smax[g * 32 + c], __float_as_uint(v));
        if (c == 0) atomicAdd(&scnt[g], 1);
    }
    __syncthreads();
    for (int i = tid; i < NG * 32; i += blockDim.x) {
        atomicAdd(&g_psum[i], ssum[i]);
        atomicMaxF(&g_pmax[i], smax[i]);
    }
    if (tid < NG) atomicAdd(&g_cnt[tid], scnt[tid]);
}

__global__ void finalout_kernel(float* __restrict__ out) {
    int tid = threadIdx.x;
    if (tid < NG * 64) {
        int g = tid >> 6, j = tid & 63;
        int cnt = g_cnt[g];
        float r;
        if (j < 32) r = g_psum[g * 32 + j] / fmaxf((float)cnt, 1.0f);
        else        r = (cnt > 0) ? g_pmax[g * 32 + (j - 32)] : 0.0f;
        out[tid] = r;
    }
}

// ---------------- launch (stream-overlapped prologue; validated R13) ----------------
extern "C" void kernel_launch(void* const* d_in, const int* in_sizes, int n_in,
                              void* d_out, int out_size) {
    const float* x     = (const float*)d_in[0];
    const int*   ei    = (const int*)d_in[1];
    const float* ea    = (const float*)d_in[2];
    const int*   batch = (const int*)d_in[3];
    const float* s1W = (const float*)d_in[4];
    const float* s1b = (const float*)d_in[5];
    const float* c1Wl = (const float*)d_in[6];
    const float* c1bl = (const float*)d_in[7];
    const float* c1Wr = (const float*)d_in[8];
    const float* c1br = (const float*)d_in[9];
    const float* c1We = (const float*)d_in[10];
    const float* c1att = (const float*)d_in[11];
    const float* c1bias = (const float*)d_in[12];
    const float* bn1g = (const float*)d_in[13];
    const float* bn1b = (const float*)d_in[14];
    const float* s2W = (const float*)d_in[15];
    const float* s2b = (const float*)d_in[16];
    const float* c2Wl = (const float*)d_in[17];
    const float* c2bl = (const float*)d_in[18];
    const float* c2Wr = (const float*)d_in[19];
    const float* c2br = (const float*)d_in[20];
    const float* c2We = (const float*)d_in[21];
    const float* c2att = (const float*)d_in[22];
    const float* c2bias = (const float*)d_in[23];
    const float* bn2g = (const float*)d_in[24];
    const float* bn2b = (const float*)d_in[25];
    float* out = (float*)d_out;

    static cudaStream_t sB = nullptr;
    static cudaEvent_t ev0 = nullptr, evB = nullptr;
    if (sB == nullptr) {
        cudaStreamCreateWithFlags(&sB, cudaStreamNonBlocking);
        cudaEventCreateWithFlags(&ev0, cudaEventDisableTiming);
        cudaEventCreateWithFlags(&evB, cudaEventDisableTiming);
    }

    cudaEventRecord(ev0, 0);
    cudaStreamWaitEvent(sB, ev0, 0);

    clear_kernel<<<2048, 256, 0, sB>>>();
    pack2_kernel<<<8, 256, 0, sB>>>(c2Wl, c2bl, c2Wr, c2br, s2W, s2b);
    easum_kernel<<<1024, 256, 0, sB>>>((const float4*)ea);
    eself_kernel<<<1, 64, 0, sB>>>(c1We, c2We);
    cudaEventRecord(evB, sB);

    pack1_kernel<<<32, 256>>>(c1Wl, c1bl, c1Wr, c1br, s1W, s1b);
    gemm1_kernel<<<dim3((N_NODES + 63) / 64, 2), 256>>>(x);

    cudaStreamWaitEvent(0, evB, 0);

    edge1_kernel<<<2048, 256>>>(ei, ea, c1We, c1att);
    final1_kernel<<<512, 256>>>(c1bias);
    bnfin1_kernel<<<1, 64>>>(bn1g, bn1b);

    gemm2_kernel<<<dim3((N_NODES + 63) / 64, 1), 256>>>(c1bias);
    edge2_kernel<<<1536, 256>>>(ei, ea, c2We, c2att);
    final2_kernel<<<512, 256>>>(c2bias);
    bnfin2_kernel<<<1, 32>>>(bn2g, bn2b);
    elu2pool_kernel<<<256, 256>>>(batch, c2bias);
    finalout_kernel<<<1, 1024>>>(out);
}

// round 17
// speedup vs baseline: 1.0844x; 1.0844x over previous
#include <cuda_runtime.h>
#include <cstdint>

#define N_NODES 50000
#define N_EDGES 800000
#define NE_TOT  (N_EDGES + N_NODES)   // 850000, self loops appended
#define NG 16

typedef unsigned long long ull;

// ---------------- scratch ----------------
__device__ __align__(16) float g_big1[N_NODES * 192];   // 0-63 xl1 | 64-127 xr1 | 128-191 hproj1
__device__ __align__(16) float g_big2[N_NODES * 96];    // 0-31 xl2 | 32-63 xr2 | 64-95 hproj2
__device__ __align__(16) float g_acc1[N_NODES * 64];
__device__ __align__(16) float g_den1[N_NODES * 2];
__device__ __align__(16) float g_acc2[N_NODES * 32];
__device__ __align__(16) float g_den2[N_NODES];
__device__ __align__(16) float g_Wcat1[128 * 192];
__device__ __align__(16) float g_bcat1[192];
__device__ __align__(16) float g_Wcat2[64 * 96];
__device__ __align__(16) float g_bcat2[96];
__device__ __align__(16) float g_easum[16];
__device__ __align__(16) float g_eself1[64];
__device__ __align__(16) float g_eself2[32];
__device__ __align__(16) float g_bnsum[128];     // [0:64) sum, [64:128) sumsq
__device__ __align__(16) float g_bnsc1[128];     // [0:64) scale, [64:128) shift
__device__ __align__(16) float g_bnsum2[64];
__device__ __align__(16) float g_bnsc2[64];
__device__ __align__(16) float g_psum[NG * 32];
__device__ __align__(16) float g_pmax[NG * 32];
__device__ int g_cnt[NG];
__device__ int g_done1;
__device__ int g_done2;

// ---------------- helpers ----------------
__device__ __forceinline__ ull pk2(float a, float b) {
    ull r; asm("mov.b64 %0,{%1,%2};" : "=l"(r) : "f"(a), "f"(b)); return r;
}
__device__ __forceinline__ float2 up2(ull v) {
    float2 r; asm("mov.b64 {%0,%1},%2;" : "=f"(r.x), "=f"(r.y) : "l"(v)); return r;
}
__device__ __forceinline__ ull fma2(ull a, ull b, ull c) {
    ull d; asm("fma.rn.f32x2 %0,%1,%2,%3;" : "=l"(d) : "l"(a), "l"(b), "l"(c)); return d;
}
__device__ __forceinline__ float lrelu(float v) { return v > 0.f ? v : 0.2f * v; }

__device__ __forceinline__ void red4(float* p, float4 v) {
    asm volatile("red.global.add.v4.f32 [%0], {%1,%2,%3,%4};"
                 :: "l"(p), "f"(v.x), "f"(v.y), "f"(v.z), "f"(v.w) : "memory");
}

__device__ __forceinline__ void atomicMaxF(float* addr, float v) {
    if (v >= 0.f) atomicMax((int*)addr, __float_as_int(v));
    else          atomicMin((unsigned int*)addr, __float_as_uint(v));
}

// ---------------- clear (vectorized) ----------------
__global__ void clear_kernel() {
    int i  = blockIdx.x * blockDim.x + threadIdx.x;
    int st = gridDim.x * blockDim.x;
    float4 z4 = make_float4(0.f, 0.f, 0.f, 0.f);
    float4* a1 = (float4*)g_acc1;
    float4* a2 = (float4*)g_acc2;
    for (int j = i; j < N_NODES * 16; j += st) a1[j] = z4;
    for (int j = i; j < N_NODES * 8;  j += st) a2[j] = z4;
    float2* d1 = (float2*)g_den1;
    for (int j = i; j < N_NODES; j += st) { d1[j] = make_float2(0.f, 0.f); g_den2[j] = 0.f; }
    if (i < 16)  g_easum[i] = 0.f;
    if (i < 128) g_bnsum[i] = 0.f;
    if (i < 64)  g_bnsum2[i] = 0.f;
    if (i < NG * 32) { g_psum[i] = 0.f; g_pmax[i] = __int_as_float(0xff800000); }
    if (i < NG)  g_cnt[i] = 0;
    if (i == 0) { g_done1 = 0; g_done2 = 0; }
}

// ---------------- weight packing ----------------
__global__ void pack1_kernel(const float* __restrict__ Wl, const float* __restrict__ bl,
                             const float* __restrict__ Wr, const float* __restrict__ br,
                             const float* __restrict__ Ws, const float* __restrict__ bs) {
    int i = blockIdx.x * blockDim.x + threadIdx.x;
    if (i < 128 * 64) {
        int k = i >> 6, j = i & 63;
        g_Wcat1[k * 192 + j]       = Wl[i];
        g_Wcat1[k * 192 + 64 + j]  = Wr[i];
        g_Wcat1[k * 192 + 128 + j] = Ws[i];
    }
    if (i < 64) { g_bcat1[i] = bl[i]; g_bcat1[64 + i] = br[i]; g_bcat1[128 + i] = bs[i]; }
}

__global__ void pack2_kernel(const float* __restrict__ Wl, const float* __restrict__ bl,
                             const float* __restrict__ Wr, const float* __restrict__ br,
                             const float* __restrict__ Ws, const float* __restrict__ bs) {
    int i = blockIdx.x * blockDim.x + threadIdx.x;
    if (i < 64 * 32) {
        int k = i >> 5, j = i & 31;
        g_Wcat2[k * 96 + j]      = Wl[i];
        g_Wcat2[k * 96 + 32 + j] = Wr[i];
        g_Wcat2[k * 96 + 64 + j] = Ws[i];
    }
    if (i < 32) { g_bcat2[i] = bl[i]; g_bcat2[32 + i] = br[i]; g_bcat2[64 + i] = bs[i]; }
}

// ---------------- edge_attr column sums ----------------
__global__ void easum_kernel(const float4* __restrict__ ea4) {
    const int NT = N_EDGES * 4;
    int tid = blockIdx.x * blockDim.x + threadIdx.x;
    int st  = gridDim.x * blockDim.x;
    int grp = tid & 3;
    float4 s = make_float4(0.f, 0.f, 0.f, 0.f);
    int i = tid;
    for (; i + 3 * st < NT; i += 4 * st) {
        float4 v0 = ea4[i];
        float4 v1 = ea4[i + st];
        float4 v2 = ea4[i + 2 * st];
        float4 v3 = ea4[i + 3 * st];
        s.x += v0.x + v1.x + v2.x + v3.x;
        s.y += v0.y + v1.y + v2.y + v3.y;
        s.z += v0.z + v1.z + v2.z + v3.z;
        s.w += v0.w + v1.w + v2.w + v3.w;
    }
    for (; i < NT; i += st) {
        float4 v = ea4[i];
        s.x += v.x; s.y += v.y; s.z += v.z; s.w += v.w;
    }
    __shared__ float sm[16];
    if (threadIdx.x < 16) sm[threadIdx.x] = 0.f;
    __syncthreads();
    atomicAdd(&sm[grp * 4 + 0], s.x);
    atomicAdd(&sm[grp * 4 + 1], s.y);
    atomicAdd(&sm[grp * 4 + 2], s.z);
    atomicAdd(&sm[grp * 4 + 3], s.w);
    __syncthreads();
    if (threadIdx.x < 16) atomicAdd(&g_easum[threadIdx.x], sm[threadIdx.x]);
}

__global__ void eself_kernel(const float* __restrict__ We1, const float* __restrict__ We2) {
    __shared__ float m[16];
    int t = threadIdx.x;
    if (t < 16) m[t] = g_easum[t] * (1.0f / N_EDGES);
    __syncthreads();
    if (t < 64) {
        float s = 0.f;
        #pragma unroll
        for (int k = 0; k < 16; k++) s += m[k] * We1[k * 64 + t];
        g_eself1[t] = s;
    }
    if (t < 32) {
        float s = 0.f;
        #pragma unroll
        for (int k = 0; k < 16; k++) s += m[k] * We2[k * 32 + t];
        g_eself2[t] = s;
    }
}

// ---------------- tiled GEMM 1 with fma.rn.f32x2 (validated) ----------------
__global__ void gemm1_kernel(const float* __restrict__ A) {
    const int K = 128, NT = 192;
    __shared__ __align__(16) float As[16 * 68];
    __shared__ __align__(8)  float Bs[16 * 100];
    const int bm = blockIdx.x * 64;
    const int bn = blockIdx.y * 96;
    const int tid = threadIdx.x;
    const int tx = tid & 15, ty = tid >> 4;
    ull acc[4][3];
    #pragma unroll
    for (int i = 0; i < 4; i++)
        #pragma unroll
        for (int j = 0; j < 3; j++) acc[i][j] = 0ull;
    const int ar = tid >> 2, ac = (tid & 3) << 2;
    for (int k0 = 0; k0 < K; k0 += 16) {
        float4 av = make_float4(0.f, 0.f, 0.f, 0.f);
        int row = bm + ar;
        if (row < N_NODES) av = *(const float4*)&A[(size_t)row * K + k0 + ac];
        As[(ac + 0) * 68 + ar] = av.x;
        As[(ac + 1) * 68 + ar] = av.y;
        As[(ac + 2) * 68 + ar] = av.z;
        As[(ac + 3) * 68 + ar] = av.w;
        #pragma unroll
        for (int i = 0; i < 6; i++) {
            int idx = tid + (i << 8);
            int r = idx / 96, cc = idx - r * 96;
            Bs[r * 100 + cc] = g_Wcat1[(k0 + r) * NT + bn + cc];
        }
        __syncthreads();
        #pragma unroll
        for (int kk = 0; kk < 16; kk++) {
            float4 a = *(const float4*)&As[kk * 68 + (ty << 2)];
            ull b0 = *(const ull*)&Bs[kk * 100 + tx * 6];
            ull b1 = *(const ull*)&Bs[kk * 100 + tx * 6 + 2];
            ull b2 = *(const ull*)&Bs[kk * 100 + tx * 6 + 4];
            ull ap;
            ap = pk2(a.x, a.x);
            acc[0][0] = fma2(ap, b0, acc[0][0]); acc[0][1] = fma2(ap, b1, acc[0][1]); acc[0][2] = fma2(ap, b2, acc[0][2]);
            ap = pk2(a.y, a.y);
            acc[1][0] = fma2(ap, b0, acc[1][0]); acc[1][1] = fma2(ap, b1, acc[1][1]); acc[1][2] = fma2(ap, b2, acc[1][2]);
            ap = pk2(a.z, a.z);
            acc[2][0] = fma2(ap, b0, acc[2][0]); acc[2][1] = fma2(ap, b1, acc[2][1]); acc[2][2] = fma2(ap, b2, acc[2][2]);
            ap = pk2(a.w, a.w);
            acc[3][0] = fma2(ap, b0, acc[3][0]); acc[3][1] = fma2(ap, b1, acc[3][1]); acc[3][2] = fma2(ap, b2, acc[3][2]);
        }
        __syncthreads();
    }
    #pragma unroll
    for (int i = 0; i < 4; i++) {
        int r = bm + (ty << 2) + i;
        if (r < N_NODES) {
            #pragma unroll
            for (int j = 0; j < 3; j++) {
                float2 v = up2(acc[i][j]);
                int cc = bn + tx * 6 + 2 * j;
                g_big1[(size_t)r * NT + cc]     = v.x + g_bcat1[cc];
                g_big1[(size_t)r * NT + cc + 1] = v.y + g_bcat1[cc + 1];
            }
        }
    }
}

// ---------------- GEMM 2 with elu1 FUSED into the A-tile load (validated R13) ----------------
__global__ void gemm2_kernel(const float* __restrict__ bias1) {
    const int K = 64, NT = 96;
    __shared__ __align__(16) float As[16 * 68];
    __shared__ __align__(8)  float Bs[16 * 100];
    const int bm = blockIdx.x * 64;
    const int bn = 0;
    const int tid = threadIdx.x;
    const int tx = tid & 15, ty = tid >> 4;
    ull acc[4][3];
    #pragma unroll
    for (int i = 0; i < 4; i++)
        #pragma unroll
        for (int j = 0; j < 3; j++) acc[i][j] = 0ull;
    const int ar = tid >> 2, ac = (tid & 3) << 2;
    for (int k0 = 0; k0 < K; k0 += 16) {
        float4 av = make_float4(0.f, 0.f, 0.f, 0.f);
        int row = bm + ar;
        if (row < N_NODES) {
            int cc = k0 + ac;
            float invd = 1.0f / (g_den1[row * 2 + (cc >> 5)] + 1e-16f);
            float4 a4 = *(const float4*)&g_acc1[(size_t)row * 64 + cc];
            float4 p4 = *(const float4*)&g_big1[(size_t)row * 192 + 128 + cc];
            float t;
            t = (a4.x * invd + bias1[cc + 0]) * g_bnsc1[cc + 0] + g_bnsc1[64 + cc + 0] + p4.x;
            av.x = t > 0.f ? t : expm1f(t);
            t = (a4.y * invd + bias1[cc + 1]) * g_bnsc1[cc + 1] + g_bnsc1[64 + cc + 1] + p4.y;
            av.y = t > 0.f ? t : expm1f(t);
            t = (a4.z * invd + bias1[cc + 2]) * g_bnsc1[cc + 2] + g_bnsc1[64 + cc + 2] + p4.z;
            av.z = t > 0.f ? t : expm1f(t);
            t = (a4.w * invd + bias1[cc + 3]) * g_bnsc1[cc + 3] + g_bnsc1[64 + cc + 3] + p4.w;
            av.w = t > 0.f ? t : expm1f(t);
        }
        As[(ac + 0) * 68 + ar] = av.x;
        As[(ac + 1) * 68 + ar] = av.y;
        As[(ac + 2) * 68 + ar] = av.z;
        As[(ac + 3) * 68 + ar] = av.w;
        #pragma unroll
        for (int i = 0; i < 6; i++) {
            int idx = tid + (i << 8);
            int r = idx / 96, cc = idx - r * 96;
            Bs[r * 100 + cc] = g_Wcat2[(k0 + r) * NT + bn + cc];
        }
        __syncthreads();
        #pragma unroll
        for (int kk = 0; kk < 16; kk++) {
            float4 a = *(const float4*)&As[kk * 68 + (ty << 2)];
            ull b0 = *(const ull*)&Bs[kk * 100 + tx * 6];
            ull b1 = *(const ull*)&Bs[kk * 100 + tx * 6 + 2];
            ull b2 = *(const ull*)&Bs[kk * 100 + tx * 6 + 4];
            ull ap;
            ap = pk2(a.x, a.x);
            acc[0][0] = fma2(ap, b0, acc[0][0]); acc[0][1] = fma2(ap, b1, acc[0][1]); acc[0][2] = fma2(ap, b2, acc[0][2]);
            ap = pk2(a.y, a.y);
            acc[1][0] = fma2(ap, b0, acc[1][0]); acc[1][1] = fma2(ap, b1, acc[1][1]); acc[1][2] = fma2(ap, b2, acc[1][2]);
            ap = pk2(a.z, a.z);
            acc[2][0] = fma2(ap, b0, acc[2][0]); acc[2][1] = fma2(ap, b1, acc[2][1]); acc[2][2] = fma2(ap, b2, acc[2][2]);
            ap = pk2(a.w, a.w);
            acc[3][0] = fma2(ap, b0, acc[3][0]); acc[3][1] = fma2(ap, b1, acc[3][1]); acc[3][2] = fma2(ap, b2, acc[3][2]);
        }
        __syncthreads();
    }
    #pragma unroll
    for (int i = 0; i < 4; i++) {
        int r = bm + (ty << 2) + i;
        if (r < N_NODES) {
            #pragma unroll
            for (int j = 0; j < 3; j++) {
                float2 v = up2(acc[i][j]);
                int cc = bn + tx * 6 + 2 * j;
                g_big2[(size_t)r * NT + cc]     = v.x + g_bcat2[cc];
                g_big2[(size_t)r * NT + cc + 1] = v.y + g_bcat2[cc + 1];
            }
        }
    }
}

// ---------------- edge kernel layer 1 (smem-We; 2 edges in flight; validated R12/R13) ----------------
__global__ void edge1_kernel(const int* __restrict__ ei, const float* __restrict__ ea,
                             const float* __restrict__ We, const float* __restrict__ att) {
    __shared__ __align__(16) float sWe[16 * 64];
    __shared__ __align__(16) float sAtt[64];
    __shared__ __align__(16) float sEself[64];
    for (int i = threadIdx.x; i < 16 * 64; i += blockDim.x) sWe[i] = We[i];
    if (threadIdx.x < 64) { sAtt[threadIdx.x] = att[threadIdx.x]; sEself[threadIdx.x] = g_eself1[threadIdx.x]; }
    __syncthreads();
    const int lane = threadIdx.x & 31;
    const int sub  = lane & 15;
    const int head = sub >> 3;
    const int half = lane >> 4;
    const int warp = threadIdx.x >> 5;
    const int nwarps = (gridDim.x * blockDim.x) >> 5;
    const int gw = blockIdx.x * (blockDim.x >> 5) + warp;
    const int npairs = (NE_TOT + 1) >> 1;
    const float4 a4  = *(const float4*)&sAtt[4 * sub];
    const float4 es4 = *(const float4*)&sEself[4 * sub];
    for (int p0 = gw; p0 < npairs; p0 += 2 * nwarps) {
        const int p1 = p0 + nwarps;
        const bool hasB = p1 < npairs;
        int eA = p0 * 2 + half;
        int eB = hasB ? (p1 * 2 + half) : 0;
        bool vA = eA < NE_TOT;
        bool vB = hasB && (eB < NE_TOT);
        int sA = 0, dA = 0, sB = 0, dB = 0;
        bool loopA = false, loopB = false;
        if (vA) {
            if (eA < N_EDGES) { sA = ei[eA]; dA = ei[N_EDGES + eA]; }
            else              { sA = dA = eA - N_EDGES; loopA = true; }
        }
        if (vB) {
            if (eB < N_EDGES) { sB = ei[eB]; dB = ei[N_EDGES + eB]; }
            else              { sB = dB = eB - N_EDGES; loopB = true; }
        }
        int exA = (vA && !loopA) ? eA : 0;
        int exB = (vB && !loopB) ? eB : 0;
        float eavA = ea[(size_t)exA * 16 + sub];
        float eavB = ea[(size_t)exB * 16 + sub];
        float4 xlA = *(const float4*)&g_big1[(size_t)sA * 192 + 4 * sub];
        float4 xrA = *(const float4*)&g_big1[(size_t)dA * 192 + 64 + 4 * sub];
        float4 xlB = *(const float4*)&g_big1[(size_t)sB * 192 + 4 * sub];
        float4 xrB = *(const float4*)&g_big1[(size_t)dB * 192 + 64 + 4 * sub];
        float4 e4A = make_float4(0.f, 0.f, 0.f, 0.f);
        float4 e4B = make_float4(0.f, 0.f, 0.f, 0.f);
        #pragma unroll
        for (int k = 0; k < 16; k++) {
            float aA = __shfl_sync(0xffffffffu, eavA, k, 16);
            float aB = __shfl_sync(0xffffffffu, eavB, k, 16);
            float4 w4 = *(const float4*)&sWe[k * 64 + 4 * sub];
            e4A.x += aA * w4.x; e4A.y += aA * w4.y; e4A.z += aA * w4.z; e4A.w += aA * w4.w;
            e4B.x += aB * w4.x; e4B.y += aB * w4.y; e4B.z += aB * w4.z; e4B.w += aB * w4.w;
        }
        if (loopA) e4A = es4;
        if (loopB) e4B = es4;
        float4 mA, mB;
        mA.x = lrelu(xlA.x + xrA.x + e4A.x);
        mA.y = lrelu(xlA.y + xrA.y + e4A.y);
        mA.z = lrelu(xlA.z + xrA.z + e4A.z);
        mA.w = lrelu(xlA.w + xrA.w + e4A.w);
        mB.x = lrelu(xlB.x + xrB.x + e4B.x);
        mB.y = lrelu(xlB.y + xrB.y + e4B.y);
        mB.z = lrelu(xlB.z + xrB.z + e4B.z);
        mB.w = lrelu(xlB.w + xrB.w + e4B.w);
        float pA = mA.x * a4.x + mA.y * a4.y + mA.z * a4.z + mA.w * a4.w;
        float pB = mB.x * a4.x + mB.y * a4.y + mB.z * a4.z + mB.w * a4.w;
        pA += __shfl_xor_sync(0xffffffffu, pA, 4);
        pB += __shfl_xor_sync(0xffffffffu, pB, 4);
        pA += __shfl_xor_sync(0xffffffffu, pA, 2);
        pB += __shfl_xor_sync(0xffffffffu, pB, 2);
        pA += __shfl_xor_sync(0xffffffffu, pA, 1);
        pB += __shfl_xor_sync(0xffffffffu, pB, 1);
        float wA = __expf(pA);
        float wB = __expf(pB);
        if (vA) {
            if ((sub & 7) == 0) atomicAdd(&g_den1[dA * 2 + head], wA);
            red4(&g_acc1[(size_t)dA * 64 + 4 * sub],
                 make_float4(wA * xlA.x, wA * xlA.y, wA * xlA.z, wA * xlA.w));
        }
        if (vB) {
            if ((sub & 7) == 0) atomicAdd(&g_den1[dB * 2 + head], wB);
            red4(&g_acc1[(size_t)dB * 64 + 4 * sub],
                 make_float4(wB * xlB.x, wB * xlB.y, wB * xlB.z, wB * xlB.w));
        }
    }
}

// ---------------- edge kernel layer 2 (smem-We; 2 quads in flight; validated R12/R13) ----------------
__global__ void edge2_kernel(const int* __restrict__ ei, const float* __restrict__ ea,
                             const float* __restrict__ We, const float* __restrict__ att) {
    __shared__ __align__(16) float sWe[16 * 32];
    __shared__ __align__(16) float sAtt[32];
    __shared__ __align__(16) float sEself[32];
    for (int i = threadIdx.x; i < 512; i += blockDim.x) sWe[i] = We[i];
    if (threadIdx.x < 32) { sAtt[threadIdx.x] = att[threadIdx.x]; sEself[threadIdx.x] = g_eself2[threadIdx.x]; }
    __syncthreads();
    const int lane = threadIdx.x & 31;
    const int grp = lane >> 3, sub = lane & 7;
    const int warp = threadIdx.x >> 5;
    const int nwarps = (gridDim.x * blockDim.x) >> 5;
    const int gw = blockIdx.x * (blockDim.x >> 5) + warp;
    const int nquads = (NE_TOT + 3) >> 2;
    const float4 a4  = *(const float4*)&sAtt[4 * sub];
    const float4 es4 = *(const float4*)&sEself[4 * sub];
    for (int q0 = gw; q0 < nquads; q0 += 2 * nwarps) {
        const int q1 = q0 + nwarps;
        const bool hasB = q1 < nquads;
        int eA = q0 * 4 + grp;
        int eB = hasB ? (q1 * 4 + grp) : 0;
        bool vA = eA < NE_TOT;
        bool vB = hasB && (eB < NE_TOT);
        int sA = 0, dA = 0, sB = 0, dB = 0;
        bool loopA = false, loopB = false;
        if (vA) {
            if (eA < N_EDGES) { sA = ei[eA]; dA = ei[N_EDGES + eA]; }
            else              { sA = dA = eA - N_EDGES; loopA = true; }
        }
        if (vB) {
            if (eB < N_EDGES) { sB = ei[eB]; dB = ei[N_EDGES + eB]; }
            else              { sB = dB = eB - N_EDGES; loopB = true; }
        }
        int exA = (vA && !loopA) ? eA : 0;
        int exB = (vB && !loopB) ? eB : 0;
        float e0A = ea[(size_t)exA * 16 + sub];
        float e1A = ea[(size_t)exA * 16 + 8 + sub];
        float e0B = ea[(size_t)exB * 16 + sub];
        float e1B = ea[(size_t)exB * 16 + 8 + sub];
        float4 xlA = *(const float4*)&g_big2[(size_t)sA * 96 + 4 * sub];
        float4 xrA = *(const float4*)&g_big2[(size_t)dA * 96 + 32 + 4 * sub];
        float4 xlB = *(const float4*)&g_big2[(size_t)sB * 96 + 4 * sub];
        float4 xrB = *(const float4*)&g_big2[(size_t)dB * 96 + 32 + 4 * sub];
        float4 e4A = make_float4(0.f, 0.f, 0.f, 0.f);
        float4 e4B = make_float4(0.f, 0.f, 0.f, 0.f);
        #pragma unroll
        for (int k = 0; k < 8; k++) {
            float aA = __shfl_sync(0xffffffffu, e0A, k, 8);
            float aB = __shfl_sync(0xffffffffu, e0B, k, 8);
            float4 w4 = *(const float4*)&sWe[k * 32 + 4 * sub];
            e4A.x += aA * w4.x; e4A.y += aA * w4.y; e4A.z += aA * w4.z; e4A.w += aA * w4.w;
            e4B.x += aB * w4.x; e4B.y += aB * w4.y; e4B.z += aB * w4.z; e4B.w += aB * w4.w;
        }
        #pragma unroll
        for (int k = 0; k < 8; k++) {
            float aA = __shfl_sync(0xffffffffu, e1A, k, 8);
            float aB = __shfl_sync(0xffffffffu, e1B, k, 8);
            float4 w4 = *(const float4*)&sWe[(8 + k) * 32 + 4 * sub];
            e4A.x += aA * w4.x; e4A.y += aA * w4.y; e4A.z += aA * w4.z; e4A.w += aA * w4.w;
            e4B.x += aB * w4.x; e4B.y += aB * w4.y; e4B.z += aB * w4.z; e4B.w += aB * w4.w;
        }
        if (loopA) e4A = es4;
        if (loopB) e4B = es4;
        float4 mA, mB;
        mA.x = lrelu(xlA.x + xrA.x + e4A.x);
        mA.y = lrelu(xlA.y + xrA.y + e4A.y);
        mA.z = lrelu(xlA.z + xrA.z + e4A.z);
        mA.w = lrelu(xlA.w + xrA.w + e4A.w);
        mB.x = lrelu(xlB.x + xrB.x + e4B.x);
        mB.y = lrelu(xlB.y + xrB.y + e4B.y);
        mB.z = lrelu(xlB.z + xrB.z + e4B.z);
        mB.w = lrelu(xlB.w + xrB.w + e4B.w);
        float pA = mA.x * a4.x + mA.y * a4.y + mA.z * a4.z + mA.w * a4.w;
        float pB = mB.x * a4.x + mB.y * a4.y + mB.z * a4.z + mB.w * a4.w;
        pA += __shfl_xor_sync(0xffffffffu, pA, 4);
        pB += __shfl_xor_sync(0xffffffffu, pB, 4);
        pA += __shfl_xor_sync(0xffffffffu, pA, 2);
        pB += __shfl_xor_sync(0xffffffffu, pB, 2);
        pA += __shfl_xor_sync(0xffffffffu, pA, 1);
        pB += __shfl_xor_sync(0xffffffffu, pB, 1);
        float wA = __expf(pA);
        float wB = __expf(pB);
        if (vA) {
            if (sub == 0) atomicAdd(&g_den2[dA], wA);
            red4(&g_acc2[(size_t)dA * 32 + 4 * sub],
                 make_float4(wA * xlA.x, wA * xlA.y, wA * xlA.z, wA * xlA.w));
        }
        if (vB) {
            if (sub == 0) atomicAdd(&g_den2[dB], wB);
            red4(&g_acc2[(size_t)dB * 32 + 4 * sub],
                 make_float4(wB * xlB.x, wB * xlB.y, wB * xlB.z, wB * xlB.w));
        }
    }
}

// ---------------- BN stats layer 1 + bnfin fused (last-block pattern) ----------------
__global__ void final1_kernel(const float* __restrict__ bias,
                              const float* __restrict__ g, const float* __restrict__ b) {
    int tid = threadIdx.x;
    int c = tid & 63;
    int h = c >> 5;
    float bb = bias[c];
    float s = 0.f, q = 0.f;
    for (int n = blockIdx.x * 4 + (tid >> 6); n < N_NODES; n += gridDim.x * 4) {
        float v = g_acc1[(size_t)n * 64 + c] / (g_den1[n * 2 + h] + 1e-16f) + bb;
        s += v; q += v * v;
    }
    __shared__ float ss[256], sq[256];
    __shared__ int slast;
    ss[tid] = s; sq[tid] = q;
    __syncthreads();
    if (tid < 64) {
        s = ss[tid] + ss[tid + 64] + ss[tid + 128] + ss[tid + 192];
        q = sq[tid] + sq[tid + 64] + sq[tid + 128] + sq[tid + 192];
        atomicAdd(&g_bnsum[tid], s);
        atomicAdd(&g_bnsum[64 + tid], q);
    }
    __threadfence();
    __syncthreads();
    if (tid == 0) {
        int t = atomicAdd(&g_done1, 1);
        slast = (t == gridDim.x - 1) ? 1 : 0;
    }
    __syncthreads();
    if (slast && tid < 64) {
        float mean = g_bnsum[tid] * (1.0f / N_NODES);
        float var  = g_bnsum[64 + tid] * (1.0f / N_NODES) - mean * mean;
        float sc   = g[tid] * rsqrtf(var + 1e-5f);
        g_bnsc1[tid] = sc;
        g_bnsc1[64 + tid] = b[tid] - mean * sc;
    }
}

// ---------------- BN stats layer 2 + bnfin fused (last-block pattern) ----------------
__global__ void final2_kernel(const float* __restrict__ bias,
                              const float* __restrict__ g, const float* __restrict__ b) {
    int tid = threadIdx.x;
    int c = tid & 31;
    float bb = bias[c];
    float s = 0.f, q = 0.f;
    for (int n = blockIdx.x * 8 + (tid >> 5); n < N_NODES; n += gridDim.x * 8) {
        float v = g_acc2[(size_t)n * 32 + c] / (g_den2[n] + 1e-16f) + bb;
        s += v; q += v * v;
    }
    __shared__ float ss[256], sq[256];
    __shared__ int slast;
    ss[tid] = s; sq[tid] = q;
    __syncthreads();
    if (tid < 32) {
        s = 0.f; q = 0.f;
        #pragma unroll
        for (int gg = 0; gg < 8; gg++) { s += ss[tid + gg * 32]; q += sq[tid + gg * 32]; }
        atomicAdd(&g_bnsum2[tid], s);
        atomicAdd(&g_bnsum2[32 + tid], q);
    }
    __threadfence();
    __syncthreads();
    if (tid == 0) {
        int t = atomicAdd(&g_done2, 1);
        slast = (t == gridDim.x - 1) ? 1 : 0;
    }
    __syncthreads();
    if (slast && tid < 32) {
        float mean = g_bnsum2[tid] * (1.0f / N_NODES);
        float var  = g_bnsum2[32 + tid] * (1.0f / N_NODES) - mean * mean;
        float sc   = g[tid] * rsqrtf(var + 1e-5f);
        g_bnsc2[tid] = sc;
        g_bnsc2[32 + tid] = b[tid] - mean * sc;
    }
}

// ---------------- elu2 + graph pooling (batch sorted; fused recompute) ----------------
__global__ void elu2pool_kernel(const int* __restrict__ batch, const float* __restrict__ bias) {
    __shared__ float ssum[NG * 32];
    __shared__ float smax[NG * 32];
    __shared__ int scnt[NG];
    int tid = threadIdx.x;
    for (int i = tid; i < NG * 32; i += blockDim.x) { ssum[i] = 0.f; smax[i] = __int_as_float(0xff800000); }
    if (tid < NG) scnt[tid] = 0;
    __syncthreads();
    int c = tid & 31;
    float bb = bias[c];
    for (int n = blockIdx.x * 8 + (tid >> 5); n < N_NODES; n += gridDim.x * 8) {
        float v = g_acc2[(size_t)n * 32 + c] / (g_den2[n] + 1e-16f) + bb;
        v = v * g_bnsc2[c] + g_bnsc2[32 + c] + g_big2[(size_t)n * 96 + 64 + c];
        v = v > 0.f ? v : expm1f(v);
        int g = batch[n];
        atomicAdd(&ssum[g * 32 + c], v);
        if (v >= 0.f) atomicMax((int*)&smax[g * 32 + c], __float_as_int(v));
        else          atomicMin((unsigned int*)&smax[g * 32 + c], __float_as_uint(v));
        if (c == 0) atomicAdd(&scnt[g], 1);
    }
    __syncthreads();
    for (int i = tid; i < NG * 32; i += blockDim.x) {
        atomicAdd(&g_psum[i], ssum[i]);
        atomicMaxF(&g_pmax[i], smax[i]);
    }
    if (tid < NG) atomicAdd(&g_cnt[tid], scnt[tid]);
}

__global__ void finalout_kernel(float* __restrict__ out) {
    int tid = threadIdx.x;
    if (tid < NG * 64) {
        int g = tid >> 6, j = tid & 63;
        int cnt = g_cnt[g];
        float r;
        if (j < 32) r = g_psum[g * 32 + j] / fmaxf((float)cnt, 1.0f);
        else        r = (cnt > 0) ? g_pmax[g * 32 + (j - 32)] : 0.0f;
        out[tid] = r;
    }
}

// ---------------- launch (stream-overlapped prologue; validated R13) ----------------
extern "C" void kernel_launch(void* const* d_in, const int* in_sizes, int n_in,
                              void* d_out, int out_size) {
    const float* x     = (const float*)d_in[0];
    const int*   ei    = (const int*)d_in[1];
    const float* ea    = (const float*)d_in[2];
    const int*   batch = (const int*)d_in[3];
    const float* s1W = (const float*)d_in[4];
    const float* s1b = (const float*)d_in[5];
    const float* c1Wl = (const float*)d_in[6];
    const float* c1bl = (const float*)d_in[7];
    const float* c1Wr = (const float*)d_in[8];
    const float* c1br = (const float*)d_in[9];
    const float* c1We = (const float*)d_in[10];
    const float* c1att = (const float*)d_in[11];
    const float* c1bias = (const float*)d_in[12];
    const float* bn1g = (const float*)d_in[13];
    const float* bn1b = (const float*)d_in[14];
    const float* s2W = (const float*)d_in[15];
    const float* s2b = (const float*)d_in[16];
    const float* c2Wl = (const float*)d_in[17];
    const float* c2bl = (const float*)d_in[18];
    const float* c2Wr = (const float*)d_in[19];
    const float* c2br = (const float*)d_in[20];
    const float* c2We = (const float*)d_in[21];
    const float* c2att = (const float*)d_in[22];
    const float* c2bias = (const float*)d_in[23];
    const float* bn2g = (const float*)d_in[24];
    const float* bn2b = (const float*)d_in[25];
    float* out = (float*)d_out;

    static cudaStream_t sB = nullptr;
    static cudaEvent_t ev0 = nullptr, evB = nullptr;
    if (sB == nullptr) {
        cudaStreamCreateWithFlags(&sB, cudaStreamNonBlocking);
        cudaEventCreateWithFlags(&ev0, cudaEventDisableTiming);
        cudaEventCreateWithFlags(&evB, cudaEventDisableTiming);
    }

    cudaEventRecord(ev0, 0);
    cudaStreamWaitEvent(sB, ev0, 0);

    clear_kernel<<<2048, 256, 0, sB>>>();
    pack2_kernel<<<8, 256, 0, sB>>>(c2Wl, c2bl, c2Wr, c2br, s2W, s2b);
    easum_kernel<<<1024, 256, 0, sB>>>((const float4*)ea);
    eself_kernel<<<1, 64, 0, sB>>>(c1We, c2We);
    cudaEventRecord(evB, sB);

    pack1_kernel<<<32, 256>>>(c1Wl, c1bl, c1Wr, c1br, s1W, s1b);
    gemm1_kernel<<<dim3((N_NODES + 63) / 64, 2), 256>>>(x);

    cudaStreamWaitEvent(0, evB, 0);

    edge1_kernel<<<2048, 256>>>(ei, ea, c1We, c1att);
    final1_kernel<<<512, 256>>>(c1bias, bn1g, bn1b);

    gemm2_kernel<<<dim3((N_NODES + 63) / 64, 1), 256>>>(c1bias);
    edge2_kernel<<<1536, 256>>>(ei, ea, c2We, c2att);
    final2_kernel<<<512, 256>>>(c2bias, bn2g, bn2b);
    elu2pool_kernel<<<256, 256>>>(batch, c2bias);
    finalout_kernel<<<1, 1024>>>(out);
}